// round 15
// baseline (speedup 1.0000x reference)
#include <cuda_runtime.h>

#define HH   48
#define HH2  2304
#define HH3  110592
#define NT   512
#define NEG_BIG (-3.402823466e38f)
#define SCF  0.35355339059327373f

// window-grouped token layout: 27 tokens/window in 7 groups of 4, each group 36 floats
#define WSTR 252
__device__ __forceinline__ int OTL(int tl) { return (tl >> 2)*36 + (tl & 3)*8; }

__device__ __forceinline__ float4 fmax4(float4 a, float4 b) {
    return make_float4(fmaxf(a.x,b.x), fmaxf(a.y,b.y), fmaxf(a.z,b.z), fmaxf(a.w,b.w));
}
__device__ __forceinline__ float hmax4(float4 a) {
    return fmaxf(fmaxf(a.x,a.y), fmaxf(a.z,a.w));
}

// CTA covers (b, head, wz, wy) and all NW windows along x.
template<int BW, int SW, int NW, int SCALE>
__device__ __forceinline__ void do_scale(
    const float* __restrict__ q, const float* __restrict__ k,
    const float* __restrict__ v, const float* __restrict__ rpb,
    float* __restrict__ out, float* sm, int rem)
{
    constexpr int X  = 3*NW;
    constexpr int SO = 9*X;
    constexpr int GB = NW*WSTR;
    const int tid = threadIdx.x;
    int wy = rem % NW; rem /= NW;
    int wz = rem % NW; rem /= NW;
    int head = rem & 1;
    int b    = rem >> 1;
    const int cb = (b*64 + (SCALE*2+head)*8) * HH3;

    float* bias125 = sm;           // raw rpb column for this head
    float* A  = sm + 128;          // pooled q
    float* Bm = A + GB;            // pooled k
    float* Cm = Bm + GB;           // pooled v
    float* so = Cm + GB;           // attention out, c-major (SO*8)
    float* sZ = so + SO*8;         // z-interp buf (scales>0) / SW8 staging

    if (tid < 125) bias125[tid] = rpb[tid*2 + head];

    // ---- pooling: xg-inner coalesced loads, window-grouped padded stores ----
    if (SW == 1) {
        for (int u = tid; u < 864; u += NT) {
            int xg = u % 12; int t = u / 12; int c = t & 7; t >>= 3;
            int py = t % 3, pz = t / 3;
            int g = cb + c*HH3 + (wz*3+pz)*HH2 + (wy*3+py)*HH + xg*4;
            float4 aq = *(const float4*)(q+g);
            float4 ak = *(const float4*)(k+g);
            float4 av = *(const float4*)(v+g);
            float vq[4] = {aq.x,aq.y,aq.z,aq.w};
            float vk[4] = {ak.x,ak.y,ak.z,ak.w};
            float vv[4] = {av.x,av.y,av.z,av.w};
            int r3 = (pz*3+py)*3;
            #pragma unroll
            for (int j = 0; j < 4; j++) {
                int px = xg*4 + j;
                int w = px / 3, mx = px - w*3;
                int p = w*WSTR + OTL(r3 + mx) + c;
                A[p] = vq[j]; Bm[p] = vk[j]; Cm[p] = vv[j];
            }
        }
    } else if (SW == 2) {
        for (int u = tid; u < 864; u += NT) {
            int xg = u % 12; int t = u / 12; int c = t & 7; t >>= 3;
            int py = t % 3, pz = t / 3;
            int z0 = wz*6 + pz*2, y0 = wy*6 + py*2;
            float4 mq = make_float4(NEG_BIG,NEG_BIG,NEG_BIG,NEG_BIG), mk = mq, mv = mq;
            #pragma unroll
            for (int dz = 0; dz < 2; dz++)
            #pragma unroll
            for (int dy = 0; dy < 2; dy++) {
                int g = cb + c*HH3 + (z0+dz)*HH2 + (y0+dy)*HH + xg*4;
                mq = fmax4(mq, *(const float4*)(q+g));
                mk = fmax4(mk, *(const float4*)(k+g));
                mv = fmax4(mv, *(const float4*)(v+g));
            }
            float rq[2] = {fmaxf(mq.x,mq.y), fmaxf(mq.z,mq.w)};
            float rk[2] = {fmaxf(mk.x,mk.y), fmaxf(mk.z,mk.w)};
            float rv[2] = {fmaxf(mv.x,mv.y), fmaxf(mv.z,mv.w)};
            int r3 = (pz*3+py)*3;
            #pragma unroll
            for (int j = 0; j < 2; j++) {
                int px = xg*2 + j;
                int w = px / 3, mx = px - w*3;
                int p = w*WSTR + OTL(r3 + mx) + c;
                A[p] = rq[j]; Bm[p] = rk[j]; Cm[p] = rv[j];
            }
        }
    } else if (SW == 4) {
        for (int u = tid; u < 864; u += NT) {
            int px = u % 12; int t = u / 12; int c = t & 7; t >>= 3;
            int py = t % 3, pz = t / 3;
            int z0 = wz*12 + pz*4, y0 = wy*12 + py*4;
            float4 mq = make_float4(NEG_BIG,NEG_BIG,NEG_BIG,NEG_BIG), mk = mq, mv = mq;
            #pragma unroll
            for (int dz = 0; dz < 4; dz++)
            #pragma unroll
            for (int dy = 0; dy < 4; dy++) {
                int g = cb + c*HH3 + (z0+dz)*HH2 + (y0+dy)*HH + px*4;
                mq = fmax4(mq, *(const float4*)(q+g));
                mk = fmax4(mk, *(const float4*)(k+g));
                mv = fmax4(mv, *(const float4*)(v+g));
            }
            int w = px / 3, mx = px - w*3;
            int p = w*WSTR + OTL((pz*3+py)*3 + mx) + c;
            A[p] = hmax4(mq); Bm[p] = hmax4(mk); Cm[p] = hmax4(mv);
        }
    } else { // SW == 8: stage1 pools x,y coalesced; stage2 pools z
        float* sA0 = sZ; float* sA1 = sZ + 3456;
        for (int u = tid; u < 6912; u += NT) {
            int xg = u % 12; int t = u / 12; int c = t & 7; t >>= 3; int py = t % 3; int z = t / 3;
            int g = cb + c*HH3 + (wz*24+z)*HH2 + (wy*24+py*8)*HH + xg*4;
            float4 mq = *(const float4*)(q+g);
            float4 mk = *(const float4*)(k+g);
            #pragma unroll
            for (int dy = 1; dy < 8; dy++) {
                mq = fmax4(mq, *(const float4*)(q+g+dy*HH));
                mk = fmax4(mk, *(const float4*)(k+g+dy*HH));
            }
            float rq = hmax4(mq), rk = hmax4(mk);
            rq = fmaxf(rq, __shfl_xor_sync(0xffffffffu, rq, 1));
            rk = fmaxf(rk, __shfl_xor_sync(0xffffffffu, rk, 1));
            if (!(xg & 1)) {
                int s = ((z*3+py)*6 + (xg>>1))*8 + c;
                sA0[s] = rq; sA1[s] = rk;
            }
        }
        __syncthreads();
        for (int u = tid; u < 432; u += NT) {
            int c = u & 7; int t = u >> 3; int px = t % 6; t /= 6; int py = t % 3; int pz = t / 3;
            float rq = NEG_BIG, rk = NEG_BIG;
            #pragma unroll
            for (int j = 0; j < 8; j++) {
                int s = (((pz*8+j)*3+py)*6 + px)*8 + c;
                rq = fmaxf(rq, sA0[s]); rk = fmaxf(rk, sA1[s]);
            }
            int w = px / 3, mx = px - w*3;
            int p = w*WSTR + OTL((pz*3+py)*3 + mx) + c;
            A[p] = rq; Bm[p] = rk;
        }
        __syncthreads();
        for (int u = tid; u < 6912; u += NT) {
            int xg = u % 12; int t = u / 12; int c = t & 7; t >>= 3; int py = t % 3; int z = t / 3;
            int g = cb + c*HH3 + (wz*24+z)*HH2 + (wy*24+py*8)*HH + xg*4;
            float4 mv = *(const float4*)(v+g);
            #pragma unroll
            for (int dy = 1; dy < 8; dy++) mv = fmax4(mv, *(const float4*)(v+g+dy*HH));
            float rv = hmax4(mv);
            rv = fmaxf(rv, __shfl_xor_sync(0xffffffffu, rv, 1));
            if (!(xg & 1)) sA0[((z*3+py)*6 + (xg>>1))*8 + c] = rv;
        }
        __syncthreads();
        for (int u = tid; u < 432; u += NT) {
            int c = u & 7; int t = u >> 3; int px = t % 6; t /= 6; int py = t % 3; int pz = t / 3;
            float rv = NEG_BIG;
            #pragma unroll
            for (int j = 0; j < 8; j++) rv = fmaxf(rv, sA0[(((pz*8+j)*3+py)*6 + px)*8 + c]);
            int w = px / 3, mx = px - w*3;
            Cm[w*WSTR + OTL((pz*3+py)*3 + mx) + c] = rv;
        }
    }
    __syncthreads();

    // ---- attention: SINGLE fused loop, bias factored post-softmax, packed accums ----
    // out = (sum_n e^{s_n} v_n)/Z + sum_n bias[m][n] v_n
    // (no max-sub: |s|<=37, e^s<=1.2e16, Z<=3e17, safely in fp32; validated R12/R14)
    const int wid = tid >> 5, lane = tid & 31;
    if ((wid < NW) && (lane < 27)) {
        const int wb = wid*WSTR;
        const int mz = lane/9, my = (lane%9)/3, mx = lane%3;
        const int mb = 25*mz + 5*my + mx;
        const int qoff = wb + OTL(lane);
        const ulonglong2 Q0 = *(const ulonglong2*)(A + qoff);
        const ulonglong2 Q1 = *(const ulonglong2*)(A + qoff + 4);
        float Z = 0.f;
        unsigned long long P0=0ull,P1=0ull,P2=0ull,P3=0ull;   // exp-weighted (f32x2)
        unsigned long long B0=0ull,B1=0ull,B2=0ull,B3=0ull;   // bias-weighted (f32x2)
        #pragma unroll
        for (int n = 0; n < 27; n++) {
            const int ph = wb + OTL(n);                          // compile-time + wb
            const int cn = 62 - 25*(n/9) - 5*((n%9)/3) - (n%3);  // compile-time
            ulonglong2 K0 = *(const ulonglong2*)(Bm+ph);
            ulonglong2 K1 = *(const ulonglong2*)(Bm+ph+4);
            unsigned long long t;
            asm("mul.rn.f32x2 %0, %1, %2;"      : "=l"(t) : "l"(Q0.x), "l"(K0.x));
            asm("fma.rn.f32x2 %0, %1, %2, %3;"  : "=l"(t) : "l"(Q0.y), "l"(K0.y), "l"(t));
            asm("fma.rn.f32x2 %0, %1, %2, %3;"  : "=l"(t) : "l"(Q1.x), "l"(K1.x), "l"(t));
            asm("fma.rn.f32x2 %0, %1, %2, %3;"  : "=l"(t) : "l"(Q1.y), "l"(K1.y), "l"(t));
            float lo, hi;
            asm("mov.b64 {%0, %1}, %2;" : "=f"(lo), "=f"(hi) : "l"(t));
            float e = __expf((lo + hi) * SCF);
            float bw = bias125[mb + cn];
            Z += e;
            ulonglong2 V0 = *(const ulonglong2*)(Cm+ph);
            ulonglong2 V1 = *(const ulonglong2*)(Cm+ph+4);
            unsigned long long e2, b2;
            asm("mov.b64 %0, {%1, %1};" : "=l"(e2) : "f"(e));
            asm("mov.b64 %0, {%1, %1};" : "=l"(b2) : "f"(bw));
            asm("fma.rn.f32x2 %0, %1, %2, %3;" : "=l"(P0) : "l"(e2), "l"(V0.x), "l"(P0));
            asm("fma.rn.f32x2 %0, %1, %2, %3;" : "=l"(P1) : "l"(e2), "l"(V0.y), "l"(P1));
            asm("fma.rn.f32x2 %0, %1, %2, %3;" : "=l"(P2) : "l"(e2), "l"(V1.x), "l"(P2));
            asm("fma.rn.f32x2 %0, %1, %2, %3;" : "=l"(P3) : "l"(e2), "l"(V1.y), "l"(P3));
            asm("fma.rn.f32x2 %0, %1, %2, %3;" : "=l"(B0) : "l"(b2), "l"(V0.x), "l"(B0));
            asm("fma.rn.f32x2 %0, %1, %2, %3;" : "=l"(B1) : "l"(b2), "l"(V0.y), "l"(B1));
            asm("fma.rn.f32x2 %0, %1, %2, %3;" : "=l"(B2) : "l"(b2), "l"(V1.x), "l"(B2));
            asm("fma.rn.f32x2 %0, %1, %2, %3;" : "=l"(B3) : "l"(b2), "l"(V1.y), "l"(B3));
        }
        float rz = 1.f / Z;
        float p0,p1,p2,p3,p4,p5,p6,p7, b0,b1,b2,b3,b4,b5,b6,b7;
        asm("mov.b64 {%0, %1}, %2;" : "=f"(p0), "=f"(p1) : "l"(P0));
        asm("mov.b64 {%0, %1}, %2;" : "=f"(p2), "=f"(p3) : "l"(P1));
        asm("mov.b64 {%0, %1}, %2;" : "=f"(p4), "=f"(p5) : "l"(P2));
        asm("mov.b64 {%0, %1}, %2;" : "=f"(p6), "=f"(p7) : "l"(P3));
        asm("mov.b64 {%0, %1}, %2;" : "=f"(b0), "=f"(b1) : "l"(B0));
        asm("mov.b64 {%0, %1}, %2;" : "=f"(b2), "=f"(b3) : "l"(B1));
        asm("mov.b64 {%0, %1}, %2;" : "=f"(b4), "=f"(b5) : "l"(B2));
        asm("mov.b64 {%0, %1}, %2;" : "=f"(b6), "=f"(b7) : "l"(B3));
        int tm = (mz*3+my)*X + wid*3 + mx;
        so[0*SO+tm] = p0*rz + b0; so[1*SO+tm] = p1*rz + b1;
        so[2*SO+tm] = p2*rz + b2; so[3*SO+tm] = p3*rz + b3;
        so[4*SO+tm] = p4*rz + b4; so[5*SO+tm] = p5*rz + b5;
        so[6*SO+tm] = p6*rz + b6; so[7*SO+tm] = p7*rz + b7;
    }
    __syncthreads();

    // ---- scatter ----
    if (SCALE == 0) {
        for (int u = tid; u < 864; u += NT) {
            int xg = u % 12; int t = u / 12; int py = t % 3; t /= 3; int pz = t % 3; int c = t / 3;
            float4 val = *(const float4*)(so + c*SO + (pz*3+py)*48 + xg*4);
            int g = cb + c*HH3 + (wz*3+pz)*HH2 + (wy*3+py)*HH + xg*4;
            *(float4*)(out+g) = val;
        }
    } else {
        for (int u = tid; u < 3456; u += NT) {   // 8*BW*3*X == 3456 for all scales
            int px = u % X; int t = u / X; int py = t % 3; t /= 3; int oz = t % BW; int c = t / BW;
            int iz = (2*oz >= BW-1) ? 1 : 0;
            float wzf = (float)(oz*2) / (float)(BW-1) - (float)iz;
            float s0 = so[c*SO + (iz*3+py)*X + px];
            float s1 = so[c*SO + ((iz+1)*3+py)*X + px];
            sZ[((c*BW+oz)*3+py)*X + px] = s0 + wzf*(s1-s0);
        }
        __syncthreads();
        constexpr int VEC = (BW == 6) ? 2 : 4;
        constexpr int NXG = 48/VEC;
        constexpr int ITEMS = 8*BW*BW*NXG;
        for (int u = tid; u < ITEMS; u += NT) {
            int xg = u % NXG; int t = u / NXG; int oy = t % BW; t /= BW; int oz = t % BW; int c = t / BW;
            int x0 = xg*VEC;
            int win = x0 / BW; int lx0 = x0 - win*BW;
            int iy = (2*oy >= BW-1) ? 1 : 0;
            float wyf = (float)(oy*2) / (float)(BW-1) - (float)iy;
            const float* z0 = sZ + ((c*BW+oz)*3+iy)*X + win*3;
            const float* z1 = z0 + X;
            float c0 = z0[0] + wyf*(z1[0]-z0[0]);
            float c1 = z0[1] + wyf*(z1[1]-z0[1]);
            float c2 = z0[2] + wyf*(z1[2]-z0[2]);
            float res[VEC];
            #pragma unroll
            for (int e = 0; e < VEC; e++) {
                int lx = lx0 + e;
                int il = (2*lx >= BW-1) ? 1 : 0;
                float wl = (float)(lx*2) / (float)(BW-1) - (float)il;
                float lo = il ? c1 : c0;
                float hi = il ? c2 : c1;
                res[e] = lo + wl*(hi-lo);
            }
            int g = cb + c*HH3 + (wz*BW+oz)*HH2 + (wy*BW+oy)*HH + x0;
            if (VEC == 4) *(float4*)(out+g) = make_float4(res[0],res[1],res[2],res[3]);
            else          *(float2*)(out+g) = make_float2(res[0],res[1]);
        }
    }
}

// Grid (heavy scales first):
//   [0,32)      scale 3: bw=24 sw=8  NW=2
//   [32,160)    scale 2: bw=12 sw=4  NW=4
//   [160,672)   scale 1: bw=6  sw=2  NW=8
//   [672,2720)  scale 0: bw=3  sw=1  NW=16
__global__ void __launch_bounds__(NT, 3)
pwa_kernel(const float* __restrict__ q, const float* __restrict__ k,
           const float* __restrict__ v, const float* __restrict__ rpb,
           float* __restrict__ out)
{
    extern __shared__ float sm[];
    int bid = blockIdx.x;
    if (bid < 32)        do_scale<24, 8, 2,  3>(q, k, v, rpb, out, sm, bid);
    else if (bid < 160)  do_scale<12, 4, 4,  2>(q, k, v, rpb, out, sm, bid - 32);
    else if (bid < 672)  do_scale< 6, 2, 8,  1>(q, k, v, rpb, out, sm, bid - 160);
    else                 do_scale< 3, 1, 16, 0>(q, k, v, rpb, out, sm, bid - 672);
}

// worst case = scale0: 128 + 3*4032 + 432*8 = 15,680 floats = 62,720 B
#define SMEM_BYTES (15680 * 4)

extern "C" void kernel_launch(void* const* d_in, const int* in_sizes, int n_in,
                              void* d_out, int out_size)
{
    const float* q   = (const float*)d_in[0];
    const float* k   = (const float*)d_in[1];
    const float* v   = (const float*)d_in[2];
    const float* rpb = (const float*)d_in[3];
    cudaFuncSetAttribute(pwa_kernel, cudaFuncAttributeMaxDynamicSharedMemorySize, SMEM_BYTES);
    pwa_kernel<<<2720, NT, SMEM_BYTES>>>(q, k, v, rpb, (float*)d_out);
}

// round 16
// speedup vs baseline: 1.1474x; 1.1474x over previous
#include <cuda_runtime.h>

#define HH   48
#define HH2  2304
#define HH3  110592
#define NT   512
#define NEG_BIG (-3.402823466e38f)
#define SCF  0.35355339059327373f
#define EXP2C 0.51006973224f   /* SCF * log2(e) */

// window-grouped token layout: 27 tokens/window in 7 groups of 4, each group 36 floats
#define WSTR 252
__device__ __forceinline__ int OTL(int tl) { return (tl >> 2)*36 + (tl & 3)*8; }

__device__ __forceinline__ float4 fmax4(float4 a, float4 b) {
    return make_float4(fmaxf(a.x,b.x), fmaxf(a.y,b.y), fmaxf(a.z,b.z), fmaxf(a.w,b.w));
}
__device__ __forceinline__ float hmax4(float4 a) {
    return fmaxf(fmaxf(a.x,a.y), fmaxf(a.z,a.w));
}

// CTA covers (b, head, wz, wy) and all NW windows along x.
template<int BW, int SW, int NW, int SCALE>
__device__ __forceinline__ void do_scale(
    const float* __restrict__ q, const float* __restrict__ k,
    const float* __restrict__ v, const float* __restrict__ rpb,
    float* __restrict__ out, float* sm, int rem)
{
    constexpr int X  = 3*NW;
    constexpr int SO = 9*X;
    constexpr int GB = NW*WSTR;
    const int tid = threadIdx.x;
    int wy = rem % NW; rem /= NW;
    int wz = rem % NW; rem /= NW;
    int head = rem & 1;
    int b    = rem >> 1;
    const int cb = (b*64 + (SCALE*2+head)*8) * HH3;

    float* bias125 = sm;           // raw rpb column for this head
    float* A  = sm + 128;          // pooled q
    float* Bm = A + GB;            // pooled k
    float* Cm = Bm + GB;           // pooled v
    float* so = Cm + GB;           // attention out, c-major (SO*8)
    float* sZ = so + SO*8;         // z-interp buf (scales>0) / SW8 staging

    if (tid < 125) bias125[tid] = rpb[tid*2 + head];

    // ---- pooling: xg-inner coalesced loads, window-grouped padded stores ----
    if (SW == 1) {
        for (int u = tid; u < 864; u += NT) {
            int xg = u % 12; int t = u / 12; int c = t & 7; t >>= 3;
            int py = t % 3, pz = t / 3;
            int g = cb + c*HH3 + (wz*3+pz)*HH2 + (wy*3+py)*HH + xg*4;
            float4 aq = *(const float4*)(q+g);
            float4 ak = *(const float4*)(k+g);
            float4 av = *(const float4*)(v+g);
            float vq[4] = {aq.x,aq.y,aq.z,aq.w};
            float vk[4] = {ak.x,ak.y,ak.z,ak.w};
            float vv[4] = {av.x,av.y,av.z,av.w};
            int r3 = (pz*3+py)*3;
            #pragma unroll
            for (int j = 0; j < 4; j++) {
                int px = xg*4 + j;
                int w = px / 3, mx = px - w*3;
                int p = w*WSTR + OTL(r3 + mx) + c;
                A[p] = vq[j]; Bm[p] = vk[j]; Cm[p] = vv[j];
            }
        }
    } else if (SW == 2) {
        for (int u = tid; u < 864; u += NT) {
            int xg = u % 12; int t = u / 12; int c = t & 7; t >>= 3;
            int py = t % 3, pz = t / 3;
            int z0 = wz*6 + pz*2, y0 = wy*6 + py*2;
            float4 mq = make_float4(NEG_BIG,NEG_BIG,NEG_BIG,NEG_BIG), mk = mq, mv = mq;
            #pragma unroll
            for (int dz = 0; dz < 2; dz++)
            #pragma unroll
            for (int dy = 0; dy < 2; dy++) {
                int g = cb + c*HH3 + (z0+dz)*HH2 + (y0+dy)*HH + xg*4;
                mq = fmax4(mq, *(const float4*)(q+g));
                mk = fmax4(mk, *(const float4*)(k+g));
                mv = fmax4(mv, *(const float4*)(v+g));
            }
            float rq[2] = {fmaxf(mq.x,mq.y), fmaxf(mq.z,mq.w)};
            float rk[2] = {fmaxf(mk.x,mk.y), fmaxf(mk.z,mk.w)};
            float rv[2] = {fmaxf(mv.x,mv.y), fmaxf(mv.z,mv.w)};
            int r3 = (pz*3+py)*3;
            #pragma unroll
            for (int j = 0; j < 2; j++) {
                int px = xg*2 + j;
                int w = px / 3, mx = px - w*3;
                int p = w*WSTR + OTL(r3 + mx) + c;
                A[p] = rq[j]; Bm[p] = rk[j]; Cm[p] = rv[j];
            }
        }
    } else if (SW == 4) {
        for (int u = tid; u < 864; u += NT) {
            int px = u % 12; int t = u / 12; int c = t & 7; t >>= 3;
            int py = t % 3, pz = t / 3;
            int z0 = wz*12 + pz*4, y0 = wy*12 + py*4;
            float4 mq = make_float4(NEG_BIG,NEG_BIG,NEG_BIG,NEG_BIG), mk = mq, mv = mq;
            #pragma unroll
            for (int dz = 0; dz < 4; dz++)
            #pragma unroll
            for (int dy = 0; dy < 4; dy++) {
                int g = cb + c*HH3 + (z0+dz)*HH2 + (y0+dy)*HH + px*4;
                mq = fmax4(mq, *(const float4*)(q+g));
                mk = fmax4(mk, *(const float4*)(k+g));
                mv = fmax4(mv, *(const float4*)(v+g));
            }
            int w = px / 3, mx = px - w*3;
            int p = w*WSTR + OTL((pz*3+py)*3 + mx) + c;
            A[p] = hmax4(mq); Bm[p] = hmax4(mk); Cm[p] = hmax4(mv);
        }
    } else { // SW == 8: stage1 pools x,y coalesced; stage2 pools z
        float* sA0 = sZ; float* sA1 = sZ + 3456;
        for (int u = tid; u < 6912; u += NT) {
            int xg = u % 12; int t = u / 12; int c = t & 7; t >>= 3; int py = t % 3; int z = t / 3;
            int g = cb + c*HH3 + (wz*24+z)*HH2 + (wy*24+py*8)*HH + xg*4;
            float4 mq = *(const float4*)(q+g);
            float4 mk = *(const float4*)(k+g);
            #pragma unroll
            for (int dy = 1; dy < 8; dy++) {
                mq = fmax4(mq, *(const float4*)(q+g+dy*HH));
                mk = fmax4(mk, *(const float4*)(k+g+dy*HH));
            }
            float rq = hmax4(mq), rk = hmax4(mk);
            rq = fmaxf(rq, __shfl_xor_sync(0xffffffffu, rq, 1));
            rk = fmaxf(rk, __shfl_xor_sync(0xffffffffu, rk, 1));
            if (!(xg & 1)) {
                int s = ((z*3+py)*6 + (xg>>1))*8 + c;
                sA0[s] = rq; sA1[s] = rk;
            }
        }
        __syncthreads();
        for (int u = tid; u < 432; u += NT) {
            int c = u & 7; int t = u >> 3; int px = t % 6; t /= 6; int py = t % 3; int pz = t / 3;
            float rq = NEG_BIG, rk = NEG_BIG;
            #pragma unroll
            for (int j = 0; j < 8; j++) {
                int s = (((pz*8+j)*3+py)*6 + px)*8 + c;
                rq = fmaxf(rq, sA0[s]); rk = fmaxf(rk, sA1[s]);
            }
            int w = px / 3, mx = px - w*3;
            int p = w*WSTR + OTL((pz*3+py)*3 + mx) + c;
            A[p] = rq; Bm[p] = rk;
        }
        __syncthreads();
        for (int u = tid; u < 6912; u += NT) {
            int xg = u % 12; int t = u / 12; int c = t & 7; t >>= 3; int py = t % 3; int z = t / 3;
            int g = cb + c*HH3 + (wz*24+z)*HH2 + (wy*24+py*8)*HH + xg*4;
            float4 mv = *(const float4*)(v+g);
            #pragma unroll
            for (int dy = 1; dy < 8; dy++) mv = fmax4(mv, *(const float4*)(v+g+dy*HH));
            float rv = hmax4(mv);
            rv = fmaxf(rv, __shfl_xor_sync(0xffffffffu, rv, 1));
            if (!(xg & 1)) sA0[((z*3+py)*6 + (xg>>1))*8 + c] = rv;
        }
        __syncthreads();
        for (int u = tid; u < 432; u += NT) {
            int c = u & 7; int t = u >> 3; int px = t % 6; t /= 6; int py = t % 3; int pz = t / 3;
            float rv = NEG_BIG;
            #pragma unroll
            for (int j = 0; j < 8; j++) rv = fmaxf(rv, sA0[(((pz*8+j)*3+py)*6 + px)*8 + c]);
            int w = px / 3, mx = px - w*3;
            Cm[w*WSTR + OTL((pz*3+py)*3 + mx) + c] = rv;
        }
    }
    __syncthreads();

    // ---- attention: fused score+exp loop (folded ex2 constant, split Z chains),
    // then weight+accumulate with combined w = e*rs + bias. Packed f32x2 math.
    // (no max-sub: |s|<=37 so e^s<=1.2e16, Z<=3e17 safely in fp32; validated R12/R14)
    const int wid = tid >> 5, lane = tid & 31;
    if ((wid < NW) && (lane < 27)) {
        const int wb = wid*WSTR;
        const int mz = lane/9, my = (lane%9)/3, mx = lane%3;
        const int mb = 25*mz + 5*my + mx;
        const int qoff = wb + OTL(lane);
        const ulonglong2 Q0 = *(const ulonglong2*)(A + qoff);
        const ulonglong2 Q1 = *(const ulonglong2*)(A + qoff + 4);
        float w27[27];
        float Z0 = 0.f, Z1 = 0.f;
        #pragma unroll
        for (int n = 0; n < 27; n++) {
            const int ph = wb + OTL(n);
            ulonglong2 K0 = *(const ulonglong2*)(Bm+ph);
            ulonglong2 K1 = *(const ulonglong2*)(Bm+ph+4);
            unsigned long long t;
            asm("mul.rn.f32x2 %0, %1, %2;"      : "=l"(t) : "l"(Q0.x), "l"(K0.x));
            asm("fma.rn.f32x2 %0, %1, %2, %3;"  : "=l"(t) : "l"(Q0.y), "l"(K0.y), "l"(t));
            asm("fma.rn.f32x2 %0, %1, %2, %3;"  : "=l"(t) : "l"(Q1.x), "l"(K1.x), "l"(t));
            asm("fma.rn.f32x2 %0, %1, %2, %3;"  : "=l"(t) : "l"(Q1.y), "l"(K1.y), "l"(t));
            float lo, hi;
            asm("mov.b64 {%0, %1}, %2;" : "=f"(lo), "=f"(hi) : "l"(t));
            float e;
            asm("ex2.approx.f32 %0, %1;" : "=f"(e) : "f"((lo + hi) * EXP2C));
            w27[n] = e;
            if (n & 1) Z1 += e; else Z0 += e;
        }
        float rs = 1.f/(Z0 + Z1);
        unsigned long long P0 = 0ull, P1 = 0ull, P2 = 0ull, P3 = 0ull;
        #pragma unroll
        for (int n = 0; n < 27; n++) {
            const int ph = wb + OTL(n);
            const int cn = 62 - 25*(n/9) - 5*((n%9)/3) - (n%3);  // compile-time
            float w = w27[n]*rs + bias125[mb + cn];
            unsigned long long w2;
            asm("mov.b64 %0, {%1, %1};" : "=l"(w2) : "f"(w));
            ulonglong2 V0 = *(const ulonglong2*)(Cm+ph);
            ulonglong2 V1 = *(const ulonglong2*)(Cm+ph+4);
            asm("fma.rn.f32x2 %0, %1, %2, %3;" : "=l"(P0) : "l"(w2), "l"(V0.x), "l"(P0));
            asm("fma.rn.f32x2 %0, %1, %2, %3;" : "=l"(P1) : "l"(w2), "l"(V0.y), "l"(P1));
            asm("fma.rn.f32x2 %0, %1, %2, %3;" : "=l"(P2) : "l"(w2), "l"(V1.x), "l"(P2));
            asm("fma.rn.f32x2 %0, %1, %2, %3;" : "=l"(P3) : "l"(w2), "l"(V1.y), "l"(P3));
        }
        float o0,o1,o2,o3,o4,o5,o6,o7;
        asm("mov.b64 {%0, %1}, %2;" : "=f"(o0), "=f"(o1) : "l"(P0));
        asm("mov.b64 {%0, %1}, %2;" : "=f"(o2), "=f"(o3) : "l"(P1));
        asm("mov.b64 {%0, %1}, %2;" : "=f"(o4), "=f"(o5) : "l"(P2));
        asm("mov.b64 {%0, %1}, %2;" : "=f"(o6), "=f"(o7) : "l"(P3));
        int tm = (mz*3+my)*X + wid*3 + mx;
        so[0*SO+tm]=o0; so[1*SO+tm]=o1; so[2*SO+tm]=o2; so[3*SO+tm]=o3;
        so[4*SO+tm]=o4; so[5*SO+tm]=o5; so[6*SO+tm]=o6; so[7*SO+tm]=o7;
    }
    __syncthreads();

    // ---- scatter ----
    if (SCALE == 0) {
        for (int u = tid; u < 864; u += NT) {
            int xg = u % 12; int t = u / 12; int py = t % 3; t /= 3; int pz = t % 3; int c = t / 3;
            float4 val = *(const float4*)(so + c*SO + (pz*3+py)*48 + xg*4);
            int g = cb + c*HH3 + (wz*3+pz)*HH2 + (wy*3+py)*HH + xg*4;
            *(float4*)(out+g) = val;
        }
    } else {
        for (int u = tid; u < 3456; u += NT) {   // 8*BW*3*X == 3456 for all scales
            int px = u % X; int t = u / X; int py = t % 3; t /= 3; int oz = t % BW; int c = t / BW;
            int iz = (2*oz >= BW-1) ? 1 : 0;
            float wzf = (float)(oz*2) / (float)(BW-1) - (float)iz;
            float s0 = so[c*SO + (iz*3+py)*X + px];
            float s1 = so[c*SO + ((iz+1)*3+py)*X + px];
            sZ[((c*BW+oz)*3+py)*X + px] = s0 + wzf*(s1-s0);
        }
        __syncthreads();
        constexpr int VEC = (BW == 6) ? 2 : 4;
        constexpr int NXG = 48/VEC;
        constexpr int ITEMS = 8*BW*BW*NXG;
        for (int u = tid; u < ITEMS; u += NT) {
            int xg = u % NXG; int t = u / NXG; int oy = t % BW; t /= BW; int oz = t % BW; int c = t / BW;
            int x0 = xg*VEC;
            int win = x0 / BW; int lx0 = x0 - win*BW;
            int iy = (2*oy >= BW-1) ? 1 : 0;
            float wyf = (float)(oy*2) / (float)(BW-1) - (float)iy;
            const float* z0 = sZ + ((c*BW+oz)*3+iy)*X + win*3;
            const float* z1 = z0 + X;
            float c0 = z0[0] + wyf*(z1[0]-z0[0]);
            float c1 = z0[1] + wyf*(z1[1]-z0[1]);
            float c2 = z0[2] + wyf*(z1[2]-z0[2]);
            float res[VEC];
            #pragma unroll
            for (int e = 0; e < VEC; e++) {
                int lx = lx0 + e;
                int il = (2*lx >= BW-1) ? 1 : 0;
                float wl = (float)(lx*2) / (float)(BW-1) - (float)il;
                float lo = il ? c1 : c0;
                float hi = il ? c2 : c1;
                res[e] = lo + wl*(hi-lo);
            }
            int g = cb + c*HH3 + (wz*BW+oz)*HH2 + (wy*BW+oy)*HH + x0;
            if (VEC == 4) *(float4*)(out+g) = make_float4(res[0],res[1],res[2],res[3]);
            else          *(float2*)(out+g) = make_float2(res[0],res[1]);
        }
    }
}

// Grid (heavy scales first):
//   [0,32)      scale 3: bw=24 sw=8  NW=2
//   [32,160)    scale 2: bw=12 sw=4  NW=4
//   [160,672)   scale 1: bw=6  sw=2  NW=8
//   [672,2720)  scale 0: bw=3  sw=1  NW=16
__global__ void __launch_bounds__(NT, 2)
pwa_kernel(const float* __restrict__ q, const float* __restrict__ k,
           const float* __restrict__ v, const float* __restrict__ rpb,
           float* __restrict__ out)
{
    extern __shared__ float sm[];
    int bid = blockIdx.x;
    if (bid < 32)        do_scale<24, 8, 2,  3>(q, k, v, rpb, out, sm, bid);
    else if (bid < 160)  do_scale<12, 4, 4,  2>(q, k, v, rpb, out, sm, bid - 32);
    else if (bid < 672)  do_scale< 6, 2, 8,  1>(q, k, v, rpb, out, sm, bid - 160);
    else                 do_scale< 3, 1, 16, 0>(q, k, v, rpb, out, sm, bid - 672);
}

// worst case = scale0: 128 + 3*4032 + 432*8 = 15,680 floats = 62,720 B
#define SMEM_BYTES (15680 * 4)

extern "C" void kernel_launch(void* const* d_in, const int* in_sizes, int n_in,
                              void* d_out, int out_size)
{
    const float* q   = (const float*)d_in[0];
    const float* k   = (const float*)d_in[1];
    const float* v   = (const float*)d_in[2];
    const float* rpb = (const float*)d_in[3];
    cudaFuncSetAttribute(pwa_kernel, cudaFuncAttributeMaxDynamicSharedMemorySize, SMEM_BYTES);
    pwa_kernel<<<2720, NT, SMEM_BYTES>>>(q, k, v, rpb, (float*)d_out);
}

// round 17
// speedup vs baseline: 1.1988x; 1.0448x over previous
#include <cuda_runtime.h>

#define HH   48
#define HH2  2304
#define HH3  110592
#define NT   256
#define NEG_BIG (-3.402823466e38f)
#define EXP2C 0.51006973224f   /* (1/sqrt(8)) * log2(e) */

// window-grouped token layout: 27 tokens/window in 7 groups of 4, each group 36 floats
#define WSTR 252
__device__ __forceinline__ int OTL(int tl) { return (tl >> 2)*36 + (tl & 3)*8; }

__device__ __forceinline__ float4 fmax4(float4 a, float4 b) {
    return make_float4(fmaxf(a.x,b.x), fmaxf(a.y,b.y), fmaxf(a.z,b.z), fmaxf(a.w,b.w));
}
__device__ __forceinline__ float hmax4(float4 a) {
    return fmaxf(fmaxf(a.x,a.y), fmaxf(a.z,a.w));
}

// CTA covers NW consecutive windows along x (one x-chunk) at fixed (b, head, wz, wy).
// Raw x extent per CTA = BW*NW = 24 floats = 6 float4 groups for EVERY scale.
template<int BW, int SW, int NW, int SCALE>
__device__ __forceinline__ void do_scale(
    const float* __restrict__ q, const float* __restrict__ k,
    const float* __restrict__ v, const float* __restrict__ rpb,
    float* __restrict__ out, float* sm, int rem)
{
    constexpr int N1 = 48 / BW;
    constexpr int XC = N1 / NW;          // x-chunks
    constexpr int X  = 3*NW;             // pooled x extent
    constexpr int SO = 9*X;
    constexpr int GB = NW*WSTR;
    const int tid = threadIdx.x;
    int xc = rem % XC; rem /= XC;
    int wy = rem % N1; rem /= N1;
    int wz = rem % N1; rem /= N1;
    int head = rem & 1;
    int b    = rem >> 1;
    const int cb  = (b*64 + (SCALE*2+head)*8) * HH3;
    const int x0g = xc * 24;             // global x base (BW*NW == 24 always)

    float* bias125 = sm;                 // raw rpb column for this head
    float* A  = sm + 128;                // pooled q
    float* Bm = A + GB;                  // pooled k
    float* Cm = Bm + GB;                 // pooled v
    float* so = Cm + GB;                 // attention out, c-major (SO*8)
    float* sZ = so + SO*8;               // z-interp buf (scales>0) / SW8 staging

    if (tid < 125) bias125[tid] = rpb[tid*2 + head];

    // ---- pooling: xg-inner coalesced loads (6 float4 groups), padded stores ----
    if (SW == 1) {
        for (int u = tid; u < 432; u += NT) {
            int xg = u % 6; int t = u / 6; int c = t & 7; t >>= 3;
            int py = t % 3, pz = t / 3;
            int g = cb + c*HH3 + (wz*3+pz)*HH2 + (wy*3+py)*HH + x0g + xg*4;
            float4 aq = *(const float4*)(q+g);
            float4 ak = *(const float4*)(k+g);
            float4 av = *(const float4*)(v+g);
            float vq[4] = {aq.x,aq.y,aq.z,aq.w};
            float vk[4] = {ak.x,ak.y,ak.z,ak.w};
            float vv[4] = {av.x,av.y,av.z,av.w};
            int r3 = (pz*3+py)*3;
            #pragma unroll
            for (int j = 0; j < 4; j++) {
                int px = xg*4 + j;               // [0,24)
                int w = px / 3, mx = px - w*3;
                int p = w*WSTR + OTL(r3 + mx) + c;
                A[p] = vq[j]; Bm[p] = vk[j]; Cm[p] = vv[j];
            }
        }
    } else if (SW == 2) {
        for (int u = tid; u < 432; u += NT) {
            int xg = u % 6; int t = u / 6; int c = t & 7; t >>= 3;
            int py = t % 3, pz = t / 3;
            int z0 = wz*6 + pz*2, y0 = wy*6 + py*2;
            float4 mq = make_float4(NEG_BIG,NEG_BIG,NEG_BIG,NEG_BIG), mk = mq, mv = mq;
            #pragma unroll
            for (int dz = 0; dz < 2; dz++)
            #pragma unroll
            for (int dy = 0; dy < 2; dy++) {
                int g = cb + c*HH3 + (z0+dz)*HH2 + (y0+dy)*HH + x0g + xg*4;
                mq = fmax4(mq, *(const float4*)(q+g));
                mk = fmax4(mk, *(const float4*)(k+g));
                mv = fmax4(mv, *(const float4*)(v+g));
            }
            float rq[2] = {fmaxf(mq.x,mq.y), fmaxf(mq.z,mq.w)};
            float rk[2] = {fmaxf(mk.x,mk.y), fmaxf(mk.z,mk.w)};
            float rv[2] = {fmaxf(mv.x,mv.y), fmaxf(mv.z,mv.w)};
            int r3 = (pz*3+py)*3;
            #pragma unroll
            for (int j = 0; j < 2; j++) {
                int px = xg*2 + j;               // [0,12)
                int w = px / 3, mx = px - w*3;
                int p = w*WSTR + OTL(r3 + mx) + c;
                A[p] = rq[j]; Bm[p] = rk[j]; Cm[p] = rv[j];
            }
        }
    } else if (SW == 4) {
        for (int u = tid; u < 432; u += NT) {
            int xg = u % 6; int t = u / 6; int c = t & 7; t >>= 3;
            int py = t % 3, pz = t / 3;
            int z0 = wz*12 + pz*4, y0 = wy*12 + py*4;
            float4 mq = make_float4(NEG_BIG,NEG_BIG,NEG_BIG,NEG_BIG), mk = mq, mv = mq;
            #pragma unroll
            for (int dz = 0; dz < 4; dz++)
            #pragma unroll
            for (int dy = 0; dy < 4; dy++) {
                int g = cb + c*HH3 + (z0+dz)*HH2 + (y0+dy)*HH + x0g + xg*4;
                mq = fmax4(mq, *(const float4*)(q+g));
                mk = fmax4(mk, *(const float4*)(k+g));
                mv = fmax4(mv, *(const float4*)(v+g));
            }
            int w = xg / 3, mx = xg - w*3;       // pooled px = xg in [0,6)
            int p = w*WSTR + OTL((pz*3+py)*3 + mx) + c;
            A[p] = hmax4(mq); Bm[p] = hmax4(mk); Cm[p] = hmax4(mv);
        }
    } else { // SW == 8 (NW==1): stage1 pools x,y; stage2 pools z
        float* sA0 = sZ; float* sA1 = sZ + 1728;
        for (int u = tid; u < 3456; u += NT) {
            int xg = u % 6; int t = u / 6; int c = t & 7; t >>= 3; int py = t % 3; int z = t / 3;
            int g = cb + c*HH3 + (wz*24+z)*HH2 + (wy*24+py*8)*HH + x0g + xg*4;
            float4 mq = *(const float4*)(q+g);
            float4 mk = *(const float4*)(k+g);
            #pragma unroll
            for (int dy = 1; dy < 8; dy++) {
                mq = fmax4(mq, *(const float4*)(q+g+dy*HH));
                mk = fmax4(mk, *(const float4*)(k+g+dy*HH));
            }
            float rq = hmax4(mq), rk = hmax4(mk);
            rq = fmaxf(rq, __shfl_xor_sync(0xffffffffu, rq, 1));
            rk = fmaxf(rk, __shfl_xor_sync(0xffffffffu, rk, 1));
            if (!(xg & 1)) {
                int s = ((z*3+py)*3 + (xg>>1))*8 + c;
                sA0[s] = rq; sA1[s] = rk;
            }
        }
        __syncthreads();
        for (int u = tid; u < 216; u += NT) {
            int c = u & 7; int t = u >> 3; int px = t % 3; t /= 3; int py = t % 3; int pz = t / 3;
            float rq = NEG_BIG, rk = NEG_BIG;
            #pragma unroll
            for (int j = 0; j < 8; j++) {
                int s = (((pz*8+j)*3+py)*3 + px)*8 + c;
                rq = fmaxf(rq, sA0[s]); rk = fmaxf(rk, sA1[s]);
            }
            int p = OTL((pz*3+py)*3 + px) + c;   // w == 0
            A[p] = rq; Bm[p] = rk;
        }
        __syncthreads();
        for (int u = tid; u < 3456; u += NT) {
            int xg = u % 6; int t = u / 6; int c = t & 7; t >>= 3; int py = t % 3; int z = t / 3;
            int g = cb + c*HH3 + (wz*24+z)*HH2 + (wy*24+py*8)*HH + x0g + xg*4;
            float4 mv = *(const float4*)(v+g);
            #pragma unroll
            for (int dy = 1; dy < 8; dy++) mv = fmax4(mv, *(const float4*)(v+g+dy*HH));
            float rv = hmax4(mv);
            rv = fmaxf(rv, __shfl_xor_sync(0xffffffffu, rv, 1));
            if (!(xg & 1)) sA0[((z*3+py)*3 + (xg>>1))*8 + c] = rv;
        }
        __syncthreads();
        for (int u = tid; u < 216; u += NT) {
            int c = u & 7; int t = u >> 3; int px = t % 3; t /= 3; int py = t % 3; int pz = t / 3;
            float rv = NEG_BIG;
            #pragma unroll
            for (int j = 0; j < 8; j++) rv = fmaxf(rv, sA0[(((pz*8+j)*3+py)*3 + px)*8 + c]);
            Cm[OTL((pz*3+py)*3 + px) + c] = rv;
        }
    }
    __syncthreads();

    // ---- attention: fused score+exp (ex2 const folded, split Z), then w = e*rs + bias.
    // No max-sub: |s|<=37 -> e^s<=1.2e16, Z<=3e17 safely in fp32 (validated R12/R14/R16).
    const int wid = tid >> 5, lane = tid & 31;
    if ((wid < NW) && (lane < 27)) {
        const int wb = wid*WSTR;
        const int mz = lane/9, my = (lane%9)/3, mx = lane%3;
        const int mb = 25*mz + 5*my + mx;
        const int qoff = wb + OTL(lane);
        const ulonglong2 Q0 = *(const ulonglong2*)(A + qoff);
        const ulonglong2 Q1 = *(const ulonglong2*)(A + qoff + 4);
        float w27[27];
        float Z0 = 0.f, Z1 = 0.f;
        #pragma unroll
        for (int n = 0; n < 27; n++) {
            const int ph = wb + OTL(n);
            ulonglong2 K0 = *(const ulonglong2*)(Bm+ph);
            ulonglong2 K1 = *(const ulonglong2*)(Bm+ph+4);
            unsigned long long t;
            asm("mul.rn.f32x2 %0, %1, %2;"      : "=l"(t) : "l"(Q0.x), "l"(K0.x));
            asm("fma.rn.f32x2 %0, %1, %2, %3;"  : "=l"(t) : "l"(Q0.y), "l"(K0.y), "l"(t));
            asm("fma.rn.f32x2 %0, %1, %2, %3;"  : "=l"(t) : "l"(Q1.x), "l"(K1.x), "l"(t));
            asm("fma.rn.f32x2 %0, %1, %2, %3;"  : "=l"(t) : "l"(Q1.y), "l"(K1.y), "l"(t));
            float lo, hi;
            asm("mov.b64 {%0, %1}, %2;" : "=f"(lo), "=f"(hi) : "l"(t));
            float e;
            asm("ex2.approx.f32 %0, %1;" : "=f"(e) : "f"((lo + hi) * EXP2C));
            w27[n] = e;
            if (n & 1) Z1 += e; else Z0 += e;
        }
        float rs = 1.f/(Z0 + Z1);
        unsigned long long P0 = 0ull, P1 = 0ull, P2 = 0ull, P3 = 0ull;
        #pragma unroll
        for (int n = 0; n < 27; n++) {
            const int ph = wb + OTL(n);
            const int cn = 62 - 25*(n/9) - 5*((n%9)/3) - (n%3);  // compile-time
            float w = w27[n]*rs + bias125[mb + cn];
            unsigned long long w2;
            asm("mov.b64 %0, {%1, %1};" : "=l"(w2) : "f"(w));
            ulonglong2 V0 = *(const ulonglong2*)(Cm+ph);
            ulonglong2 V1 = *(const ulonglong2*)(Cm+ph+4);
            asm("fma.rn.f32x2 %0, %1, %2, %3;" : "=l"(P0) : "l"(w2), "l"(V0.x), "l"(P0));
            asm("fma.rn.f32x2 %0, %1, %2, %3;" : "=l"(P1) : "l"(w2), "l"(V0.y), "l"(P1));
            asm("fma.rn.f32x2 %0, %1, %2, %3;" : "=l"(P2) : "l"(w2), "l"(V1.x), "l"(P2));
            asm("fma.rn.f32x2 %0, %1, %2, %3;" : "=l"(P3) : "l"(w2), "l"(V1.y), "l"(P3));
        }
        float o0,o1,o2,o3,o4,o5,o6,o7;
        asm("mov.b64 {%0, %1}, %2;" : "=f"(o0), "=f"(o1) : "l"(P0));
        asm("mov.b64 {%0, %1}, %2;" : "=f"(o2), "=f"(o3) : "l"(P1));
        asm("mov.b64 {%0, %1}, %2;" : "=f"(o4), "=f"(o5) : "l"(P2));
        asm("mov.b64 {%0, %1}, %2;" : "=f"(o6), "=f"(o7) : "l"(P3));
        int tm = (mz*3+my)*X + wid*3 + mx;
        so[0*SO+tm]=o0; so[1*SO+tm]=o1; so[2*SO+tm]=o2; so[3*SO+tm]=o3;
        so[4*SO+tm]=o4; so[5*SO+tm]=o5; so[6*SO+tm]=o6; so[7*SO+tm]=o7;
    }
    __syncthreads();

    // ---- scatter ----
    if (SCALE == 0) {
        for (int u = tid; u < 432; u += NT) {
            int xg = u % 6; int t = u / 6; int py = t % 3; t /= 3; int pz = t % 3; int c = t / 3;
            float4 val = *(const float4*)(so + c*SO + (pz*3+py)*X + xg*4);
            int g = cb + c*HH3 + (wz*3+pz)*HH2 + (wy*3+py)*HH + x0g + xg*4;
            *(float4*)(out+g) = val;
        }
    } else {
        for (int u = tid; u < 1728; u += NT) {   // 8*BW*3*X == 1728 for all scales
            int px = u % X; int t = u / X; int py = t % 3; t /= 3; int oz = t % BW; int c = t / BW;
            int iz = (2*oz >= BW-1) ? 1 : 0;
            float wzf = (float)(oz*2) / (float)(BW-1) - (float)iz;
            float s0 = so[c*SO + (iz*3+py)*X + px];
            float s1 = so[c*SO + ((iz+1)*3+py)*X + px];
            sZ[((c*BW+oz)*3+py)*X + px] = s0 + wzf*(s1-s0);
        }
        __syncthreads();
        constexpr int VEC = (BW == 6) ? 2 : 4;
        constexpr int NXG = 24/VEC;              // raw x extent = 24
        constexpr int ITEMS = 8*BW*BW*NXG;
        for (int u = tid; u < ITEMS; u += NT) {
            int xg = u % NXG; int t = u / NXG; int oy = t % BW; t /= BW; int oz = t % BW; int c = t / BW;
            int x0 = xg*VEC;
            int win = x0 / BW; int lx0 = x0 - win*BW;
            int iy = (2*oy >= BW-1) ? 1 : 0;
            float wyf = (float)(oy*2) / (float)(BW-1) - (float)iy;
            const float* z0 = sZ + ((c*BW+oz)*3+iy)*X + win*3;
            const float* z1 = z0 + X;
            float c0 = z0[0] + wyf*(z1[0]-z0[0]);
            float c1 = z0[1] + wyf*(z1[1]-z0[1]);
            float c2 = z0[2] + wyf*(z1[2]-z0[2]);
            float res[VEC];
            #pragma unroll
            for (int e = 0; e < VEC; e++) {
                int lx = lx0 + e;
                int il = (2*lx >= BW-1) ? 1 : 0;
                float wl = (float)(lx*2) / (float)(BW-1) - (float)il;
                float lo = il ? c1 : c0;
                float hi = il ? c2 : c1;
                res[e] = lo + wl*(hi-lo);
            }
            int g = cb + c*HH3 + (wz*BW+oz)*HH2 + (wy*BW+oy)*HH + x0g + x0;
            if (VEC == 4) *(float4*)(out+g) = make_float4(res[0],res[1],res[2],res[3]);
            else          *(float2*)(out+g) = make_float2(res[0],res[1]);
        }
    }
}

// Grid (heavy scales first); every CTA covers a 24-float x-chunk:
//   [0,64)       scale 3: bw=24 sw=8  NW=1  XC=2
//   [64,320)     scale 2: bw=12 sw=4  NW=2  XC=2
//   [320,1344)   scale 1: bw=6  sw=2  NW=4  XC=2
//   [1344,5440)  scale 0: bw=3  sw=1  NW=8  XC=2
__global__ void __launch_bounds__(NT, 4)
pwa_kernel(const float* __restrict__ q, const float* __restrict__ k,
           const float* __restrict__ v, const float* __restrict__ rpb,
           float* __restrict__ out)
{
    extern __shared__ float sm[];
    int bid = blockIdx.x;
    if (bid < 64)         do_scale<24, 8, 1, 3>(q, k, v, rpb, out, sm, bid);
    else if (bid < 320)   do_scale<12, 4, 2, 2>(q, k, v, rpb, out, sm, bid - 64);
    else if (bid < 1344)  do_scale< 6, 2, 4, 1>(q, k, v, rpb, out, sm, bid - 320);
    else                  do_scale< 3, 1, 8, 0>(q, k, v, rpb, out, sm, bid - 1344);
}

// worst case = scale0: 128 + 3*(8*252) + 216*8 = 7904 floats = 31,616 B
#define SMEM_BYTES (7904 * 4)

extern "C" void kernel_launch(void* const* d_in, const int* in_sizes, int n_in,
                              void* d_out, int out_size)
{
    const float* q   = (const float*)d_in[0];
    const float* k   = (const float*)d_in[1];
    const float* v   = (const float*)d_in[2];
    const float* rpb = (const float*)d_in[3];
    cudaFuncSetAttribute(pwa_kernel, cudaFuncAttributeMaxDynamicSharedMemorySize, SMEM_BYTES);
    pwa_kernel<<<5440, NT, SMEM_BYTES>>>(q, k, v, rpb, (float*)d_out);
}